// round 12
// baseline (speedup 1.0000x reference)
#include <cuda_runtime.h>
#include <cuda_fp16.h>
#include <cstdint>

// Problem constants
#define P_     4096
#define B_     32
#define FEAT_  512
#define ATTN_  512
#define NH_    8
#define HD_    64
#define NROWS  (P_ * B_)          // 131072 rows of X (p,b)
#define CTX_N  (B_ * ATTN_)       // context floats (output offset for weight)
#define NCHUNK 32                 // P chunks for pass C
#define PCH    (P_ / NCHUNK)      // 128 pixels per chunk

// ---- device scratch (static: allocation-free rule) ----
__device__ __half g_Mh[ATTN_ * FEAT_];                  // folded weight fp16, K-major [col][f]
__device__ float g_c[B_ * ATTN_];                       // per-batch bias [b][col]
__device__ float g_scores[B_ * NH_ * P_];               // [b*8+h][p]
__device__ float g_m[B_ * NH_];
__device__ float g_l[B_ * NH_];
__device__ float g_ypart[NCHUNK * B_ * NH_ * FEAT_];    // deterministic partial sums

// ============================================================
// helpers
// ============================================================
__device__ __forceinline__ uint32_t smem_u32(const void* p) {
    uint32_t a;
    asm("{ .reg .u64 t; cvta.to.shared.u64 t, %1; cvt.u32.u64 %0, t; }" : "=r"(a) : "l"(p));
    return a;
}
__device__ __forceinline__ uint32_t pack_h2(float lo, float hi) {
    uint32_t r;   // cvt.rn.f16x2.f32 d, a, b : a -> high half, b -> low half
    asm("cvt.rn.f16x2.f32 %0, %1, %2;" : "=r"(r) : "f"(hi), "f"(lo));
    return r;
}
__device__ __forceinline__ float tanha(float x) {
    float r;
    asm("tanh.approx.f32 %0, %1;" : "=f"(r) : "f"(x));
    return r;
}
#define CP_ASYNC16(dst, src)  asm volatile("cp.async.cg.shared.global [%0], [%1], 16;" :: "r"(dst), "l"(src))
#define CP_COMMIT()           asm volatile("cp.async.commit_group;" ::: "memory")
#define CP_WAIT(n)            asm volatile("cp.async.wait_group %0;" :: "n"(n) : "memory")

// fp16 MMA m16n8k16, fp16 accumulate (2 c-regs = half2 pairs)
__device__ __forceinline__ void mma_f16acc(uint32_t* d, const uint32_t* a, const uint32_t* b) {
    asm volatile(
        "mma.sync.aligned.m16n8k16.row.col.f16.f16.f16.f16 "
        "{%0,%1}, {%2,%3,%4,%5}, {%6,%7}, {%0,%1};"
        : "+r"(d[0]), "+r"(d[1])
        : "r"(a[0]), "r"(a[1]), "r"(a[2]), "r"(a[3]), "r"(b[0]), "r"(b[1]));
}
// promote f16x2 segment accumulators into fp32, matching f32-acc layout:
// seg[0] = (row q, cols 2r,2r+1), seg[1] = (row q+8, cols 2r,2r+1)
__device__ __forceinline__ void promote_seg(float* f, const uint32_t* s) {
    __half2 h0 = *reinterpret_cast<const __half2*>(&s[0]);
    __half2 h1 = *reinterpret_cast<const __half2*>(&s[1]);
    float2 lo = __half22float2(h0);
    float2 hi = __half22float2(h1);
    f[0] += lo.x; f[1] += lo.y;
    f[2] += hi.x; f[3] += hi.y;
}

// ============================================================
// prep_c: hid = last_hidden @ Ua_w + Ua_b;  then
// c[b,col] = (Wa_b_h @ Wa2)[j] + Wa2_b[j] + (hid_bh @ Ua2)[j] + Ua2_b[j]
// ============================================================
__global__ void prep_c(const float* __restrict__ lh,  const float* __restrict__ Ua_w,
                       const float* __restrict__ Ua_b, const float* __restrict__ Wa_b,
                       const float* __restrict__ Wa2_w, const float* __restrict__ Wa2_b,
                       const float* __restrict__ Ua2_w, const float* __restrict__ Ua2_b) {
    __shared__ float hid[ATTN_];
    int b = blockIdx.x, col = threadIdx.x;
    float acc = Ua_b[col];
    for (int f = 0; f < FEAT_; f++) acc += lh[b * FEAT_ + f] * Ua_w[f * ATTN_ + col];
    hid[col] = acc;
    __syncthreads();
    int h = col >> 6, j = col & 63;
    float c = Wa2_b[j] + Ua2_b[j];
    for (int k = 0; k < HD_; k++) {
        c += hid[h * HD_ + k] * Ua2_w[k * HD_ + j];
        c += Wa_b[h * HD_ + k] * Wa2_w[k * HD_ + j];
    }
    g_c[b * ATTN_ + col] = c;
}

// ============================================================
// prep_M: M[f, h*64+j] = sum_k Wa_w[f, h*64+k] * Wa2_w[k, j]
// stored as fp16, K-major: g_Mh[col * 512 + f]
// ============================================================
__global__ void prep_M(const float* __restrict__ Wa_w, const float* __restrict__ Wa2_w) {
    __shared__ float wrow[ATTN_];
    int f = blockIdx.x, col = threadIdx.x;
    wrow[col] = Wa_w[f * ATTN_ + col];
    __syncthreads();
    int h = col >> 6, j = col & 63;
    float acc = 0.f;
    for (int k = 0; k < HD_; k++) acc += wrow[h * HD_ + k] * Wa2_w[k * HD_ + j];
    g_Mh[col * FEAT_ + f] = __float2half_rn(acc);
}

// ============================================================
// passA_mma: T = X @ M via mma.sync fp16 (f16 accumulate, segmented fp32
// promotion every 4 chunks = K128); tanh + va-dot -> scores.
// CTA: BM=128 x BN=128 (2 heads), BK=32, 3-stage cp.async, 1 sync/chunk.
// 8 warps: 4(M) x 2(N); warp tile 32x64.
// ============================================================
#define BK     32
#define NKT    (FEAT_ / BK)          // 16 chunks
#define NSTAGE 3
#define SEGCH  4                     // chunks per fp16-acc segment (K=128)
#define XS_STRIDE 40                 // floats per row
#define MS_STRIDE 56                 // halves per row
#define XSZ    (128 * XS_STRIDE * 4) // 20480 B per stage
#define MSZ    (128 * MS_STRIDE * 2) // 14336 B per stage
#define OFF_M_BASE (NSTAGE * XSZ)    // 61440
#define OFF_VA     (OFF_M_BASE + NSTAGE * MSZ)   // 104448
#define SMEM_TOT   (OFF_VA + 256)                // 104704 bytes

__global__ void __launch_bounds__(256, 2) passA_mma(const float* __restrict__ X,
                                                    const float* __restrict__ va_w,
                                                    const float* __restrict__ va_b) {
    extern __shared__ char smc[];
    const uint32_t sbase = smem_u32(smc);
    const int tid = threadIdx.x;
    const int wid = tid >> 5, lane = tid & 31;
    const int q = lane >> 2, r = lane & 3;      // quad row / quad lane
    const int warp_m = wid & 3, warp_n = wid >> 2;
    const int nbase = blockIdx.x * 128;
    const int rowbase = blockIdx.y * 128;
    const int head = (nbase >> 6) + warp_n;

    if (tid < 64) ((float*)(smc + OFF_VA))[tid] = va_w[tid];

    // ---- chunk loader: X 1024x16B + M 512x16B => 6 cp.async / thread ----
    auto load_chunk = [&](int kt, int st) {
        int k0 = kt * BK;
        uint32_t xb = sbase + st * XSZ;
        uint32_t mb = sbase + OFF_M_BASE + st * MSZ;
#pragma unroll
        for (int t = 0; t < 4; t++) {
            int g = tid + t * 256;
            int row = g >> 3, qq = g & 7;       // 8 x 16B per 32-float row
            uint32_t dst = xb + row * (XS_STRIDE * 4) + qq * 16;
            const float* src = X + (size_t)(rowbase + row) * FEAT_ + k0 + qq * 4;
            CP_ASYNC16(dst, src);
        }
#pragma unroll
        for (int t = 0; t < 2; t++) {
            int g = tid + t * 256;
            int n = g >> 2, qq = g & 3;         // 4 x 16B per 32-half row
            uint32_t dst = mb + n * (MS_STRIDE * 2) + qq * 16;
            const __half* src = g_Mh + (size_t)(nbase + n) * FEAT_ + k0 + qq * 8;
            CP_ASYNC16(dst, src);
        }
        CP_COMMIT();
    };

    float facc[2][8][4];                         // fp32 master accumulators
    uint32_t seg[2][8][2];                       // fp16x2 segment accumulators
#pragma unroll
    for (int mt = 0; mt < 2; mt++)
#pragma unroll
        for (int nt = 0; nt < 8; nt++) {
#pragma unroll
            for (int e = 0; e < 4; e++) facc[mt][nt][e] = 0.f;
            seg[mt][nt][0] = 0u; seg[mt][nt][1] = 0u;
        }

    // preamble: fill stages 0,1
    load_chunk(0, 0);
    load_chunk(1, 1);

    int bf = 0;                                  // stage of chunk kt
    int bn = 2;                                  // stage for chunk kt+2
    for (int kt = 0; kt < NKT; kt++) {
        if (kt < NKT - 1) { CP_WAIT(1); }        // group kt complete (kt+1 may pend)
        else             { CP_WAIT(0); }
        __syncthreads();                          // visibility + all warps done with kt-1
        if (kt + 2 < NKT) load_chunk(kt + 2, bn); // into buffer freed by chunk kt-1

        const float* xs = (const float*)(smc + bf * XSZ);
        const __half* ms = (const __half*)(smc + OFF_M_BASE + bf * MSZ);
#pragma unroll
        for (int kk = 0; kk < 2; kk++) {        // two k16 steps per 32-chunk
            int k0 = kk * 16;
            uint32_t afr[2][4];
#pragma unroll
            for (int mt = 0; mt < 2; mt++) {
                int row = warp_m * 32 + mt * 16 + q;
                float2 v0 = *reinterpret_cast<const float2*>(&xs[row * XS_STRIDE + k0 + r * 2]);
                float2 v1 = *reinterpret_cast<const float2*>(&xs[(row + 8) * XS_STRIDE + k0 + r * 2]);
                float2 v2 = *reinterpret_cast<const float2*>(&xs[row * XS_STRIDE + k0 + r * 2 + 8]);
                float2 v3 = *reinterpret_cast<const float2*>(&xs[(row + 8) * XS_STRIDE + k0 + r * 2 + 8]);
                afr[mt][0] = pack_h2(v0.x, v0.y);
                afr[mt][1] = pack_h2(v1.x, v1.y);
                afr[mt][2] = pack_h2(v2.x, v2.y);
                afr[mt][3] = pack_h2(v3.x, v3.y);
            }
#pragma unroll
            for (int ng = 0; ng < 2; ng++) {     // split nt to bound live B frags
                uint32_t bfr[4][2];
#pragma unroll
                for (int nti = 0; nti < 4; nti++) {
                    int nt = ng * 4 + nti;
                    int n = warp_n * 64 + nt * 8 + q;
                    bfr[nti][0] = *reinterpret_cast<const uint32_t*>(&ms[n * MS_STRIDE + k0 + r * 2]);
                    bfr[nti][1] = *reinterpret_cast<const uint32_t*>(&ms[n * MS_STRIDE + k0 + r * 2 + 8]);
                }
#pragma unroll
                for (int mt = 0; mt < 2; mt++)
#pragma unroll
                    for (int nti = 0; nti < 4; nti++)
                        mma_f16acc(seg[mt][ng * 4 + nti], afr[mt], bfr[nti]);
            }
        }
        if ((kt & (SEGCH - 1)) == (SEGCH - 1)) { // promote every SEGCH chunks
#pragma unroll
            for (int mt = 0; mt < 2; mt++)
#pragma unroll
                for (int nt = 0; nt < 8; nt++) {
                    promote_seg(facc[mt][nt], seg[mt][nt]);
                    seg[mt][nt][0] = 0u; seg[mt][nt][1] = 0u;
                }
        }
        bf = (bf == NSTAGE - 1) ? 0 : bf + 1;
        bn = (bn == NSTAGE - 1) ? 0 : bn + 1;
    }

    // ---- epilogue: tanh + va-dot, quad reduction, score write ----
    float vb = va_b[0];
    const float* va_s = (const float*)(smc + OFF_VA);
#pragma unroll
    for (int mt = 0; mt < 2; mt++) {
#pragma unroll
        for (int ro = 0; ro < 2; ro++) {
            int rglob = rowbase + warp_m * 32 + mt * 16 + q + ro * 8;
            int b = rglob & (B_ - 1), p = rglob >> 5;
            const float* crow = &g_c[b * ATTN_ + head * HD_];
            float s = 0.f;
#pragma unroll
            for (int nt = 0; nt < 8; nt++) {
                int col = nt * 8 + r * 2;
                float2 cc = *reinterpret_cast<const float2*>(&crow[col]);
                s += tanha(facc[mt][nt][ro * 2 + 0] + cc.x) * va_s[col];
                s += tanha(facc[mt][nt][ro * 2 + 1] + cc.y) * va_s[col + 1];
            }
            s += __shfl_xor_sync(0xffffffffu, s, 1, 4);
            s += __shfl_xor_sync(0xffffffffu, s, 2, 4);
            if (r == 0) g_scores[(b * NH_ + head) * P_ + p] = s + vb;
        }
    }
}

// ============================================================
// passB: softmax stats (max, sum-exp) over P per (b,h)
// ============================================================
__global__ void passB() {
    int bh = blockIdx.x;
    const float* s = &g_scores[bh * P_];
    __shared__ float red[256];
    int tid = threadIdx.x;
    float m = -1e30f;
    for (int i = tid; i < P_; i += 256) m = fmaxf(m, s[i]);
    red[tid] = m; __syncthreads();
    for (int st = 128; st > 0; st >>= 1) {
        if (tid < st) red[tid] = fmaxf(red[tid], red[tid + st]);
        __syncthreads();
    }
    m = red[0]; __syncthreads();
    float l = 0.f;
    for (int i = tid; i < P_; i += 256) l += expf(s[i] - m);
    red[tid] = l; __syncthreads();
    for (int st = 128; st > 0; st >>= 1) {
        if (tid < st) red[tid] += red[tid + st];
        __syncthreads();
    }
    if (tid == 0) { g_m[bh] = m; g_l[bh] = red[0]; }
}

// ============================================================
// passC: per (chunk, b): w = exp(s-m)/l; writes weight output;
// partial y_{b,h} += sum_p w * x_pb (deterministic per-chunk partials)
// ============================================================
__global__ __launch_bounds__(256) void passC(const float* __restrict__ X, float* __restrict__ out) {
    int chunk = blockIdx.x, b = blockIdx.y;
    int p0 = chunk * PCH;
    int tid = threadIdx.x;
    __shared__ float m_s[NH_], li_s[NH_];
    __shared__ float w_s[PCH * NH_];   // [p_local][h]
    if (tid < NH_) { m_s[tid] = g_m[b * NH_ + tid]; li_s[tid] = 1.f / g_l[b * NH_ + tid]; }
    __syncthreads();
    for (int idx = tid; idx < PCH * NH_; idx += 256) {
        int pl = idx >> 3, h = idx & 7;
        float s = g_scores[(b * NH_ + h) * P_ + p0 + pl];
        w_s[idx] = expf(s - m_s[h]) * li_s[h];
    }
    __syncthreads();
    // weight output = mean over heads
    if (tid < PCH) {
        float sum = 0.f;
#pragma unroll
        for (int h = 0; h < NH_; h++) sum += w_s[tid * NH_ + h];
        out[CTX_N + (p0 + tid) * B_ + b] = sum * (1.0f / NH_);
    }
    // weighted reduction of X rows; each thread owns cols tid and tid+256
    float acc[NH_][2];
#pragma unroll
    for (int h = 0; h < NH_; h++) { acc[h][0] = 0.f; acc[h][1] = 0.f; }
#pragma unroll 4
    for (int pl = 0; pl < PCH; pl++) {
        const float* xr = &X[(size_t)((p0 + pl) * B_ + b) * FEAT_];
        float x0 = xr[tid], x1 = xr[tid + 256];
#pragma unroll
        for (int h = 0; h < NH_; h++) {
            float w = w_s[pl * NH_ + h];
            acc[h][0] += w * x0;
            acc[h][1] += w * x1;
        }
    }
    float* yp = &g_ypart[(size_t)chunk * (B_ * NH_ * FEAT_) + (b * NH_) * FEAT_];
#pragma unroll
    for (int h = 0; h < NH_; h++) {
        yp[h * FEAT_ + tid]       = acc[h][0];
        yp[h * FEAT_ + tid + 256] = acc[h][1];
    }
}

// ============================================================
// passD: y = sum over chunks of partials; context = y @ Wa_w(head slice) + Wa_b
// ============================================================
__global__ void passD(const float* __restrict__ Wa_w, const float* __restrict__ Wa_b,
                      float* __restrict__ out) {
    int b = blockIdx.x, col = threadIdx.x;
    __shared__ float y_s[NH_ * FEAT_];
    for (int idx = col; idx < NH_ * FEAT_; idx += 512) {
        float acc = 0.f;
        for (int ch = 0; ch < NCHUNK; ch++)
            acc += g_ypart[(size_t)ch * (B_ * NH_ * FEAT_) + b * (NH_ * FEAT_) + idx];
        y_s[idx] = acc;
    }
    __syncthreads();
    int h = col >> 6;
    float acc = Wa_b[col];
    const float* yrow = &y_s[h * FEAT_];
    for (int f = 0; f < FEAT_; f++) acc += yrow[f] * Wa_w[f * ATTN_ + col];
    out[b * ATTN_ + col] = acc;
}

// ============================================================
extern "C" void kernel_launch(void* const* d_in, const int* in_sizes, int n_in,
                              void* d_out, int out_size) {
    (void)in_sizes; (void)n_in; (void)out_size;
    const float* lh    = (const float*)d_in[0];   // last_hidden   [1,B,512]
    const float* X     = (const float*)d_in[1];   // encoder_outputs [P,B,512]
    const float* Wa_w  = (const float*)d_in[2];
    const float* Wa_b  = (const float*)d_in[3];
    const float* Ua_w  = (const float*)d_in[4];
    const float* Ua_b  = (const float*)d_in[5];
    const float* Wa2_w = (const float*)d_in[6];
    const float* Wa2_b = (const float*)d_in[7];
    const float* Ua2_w = (const float*)d_in[8];
    const float* Ua2_b = (const float*)d_in[9];
    const float* va_w  = (const float*)d_in[10];
    const float* va_b  = (const float*)d_in[11];
    float* out = (float*)d_out;

    cudaFuncSetAttribute(passA_mma, cudaFuncAttributeMaxDynamicSharedMemorySize, SMEM_TOT);

    prep_c<<<B_, ATTN_>>>(lh, Ua_w, Ua_b, Wa_b, Wa2_w, Wa2_b, Ua2_w, Ua2_b);
    prep_M<<<FEAT_, ATTN_>>>(Wa_w, Wa2_w);
    passA_mma<<<dim3(ATTN_ / 128, NROWS / 128), 256, SMEM_TOT>>>(X, va_w, va_b);
    passB<<<B_ * NH_, 256>>>();
    passC<<<dim3(NCHUNK, B_), 256>>>(X, out);
    passD<<<B_, ATTN_>>>(Wa_w, Wa_b, out);
}

// round 13
// speedup vs baseline: 1.0037x; 1.0037x over previous
#include <cuda_runtime.h>
#include <cuda_fp16.h>
#include <cstdint>

// Problem constants
#define P_     4096
#define B_     32
#define FEAT_  512
#define ATTN_  512
#define NH_    8
#define HD_    64
#define NROWS  (P_ * B_)          // 131072 rows of X (p,b)
#define CTX_N  (B_ * ATTN_)       // context floats (output offset for weight)
#define NCHUNK 32                 // P chunks for pass C
#define PCH    (P_ / NCHUNK)      // 128 pixels per chunk

// ---- device scratch (static: allocation-free rule) ----
__device__ __half g_Mh[ATTN_ * FEAT_];                  // folded weight fp16, K-major [col][f]
__device__ float g_c[B_ * ATTN_];                       // per-batch bias [b][col]
__device__ float g_scores[B_ * NH_ * P_];               // [b*8+h][p]
__device__ float g_m[B_ * NH_];
__device__ float g_l[B_ * NH_];
__device__ float g_ypart[NCHUNK * B_ * NH_ * FEAT_];    // deterministic partial sums

// ============================================================
// helpers
// ============================================================
__device__ __forceinline__ uint32_t smem_u32(const void* p) {
    uint32_t a;
    asm("{ .reg .u64 t; cvta.to.shared.u64 t, %1; cvt.u32.u64 %0, t; }" : "=r"(a) : "l"(p));
    return a;
}
__device__ __forceinline__ uint32_t pack_h2(float lo, float hi) {
    uint32_t r;   // cvt.rn.f16x2.f32 d, a, b : a -> high half, b -> low half
    asm("cvt.rn.f16x2.f32 %0, %1, %2;" : "=r"(r) : "f"(hi), "f"(lo));
    return r;
}
__device__ __forceinline__ float tanha(float x) {
    float r;
    asm("tanh.approx.f32 %0, %1;" : "=f"(r) : "f"(x));
    return r;
}
#define CP_ASYNC16(dst, src)  asm volatile("cp.async.cg.shared.global [%0], [%1], 16;" :: "r"(dst), "l"(src))
#define CP_COMMIT()           asm volatile("cp.async.commit_group;" ::: "memory")
#define CP_WAIT(n)            asm volatile("cp.async.wait_group %0;" :: "n"(n) : "memory")

// fp16 MMA m16n8k16, fp32 accumulate
__device__ __forceinline__ void mma_f16(float* d, const uint32_t* a, const uint32_t* b) {
    asm volatile(
        "mma.sync.aligned.m16n8k16.row.col.f32.f16.f16.f32 "
        "{%0,%1,%2,%3}, {%4,%5,%6,%7}, {%8,%9}, {%0,%1,%2,%3};"
        : "+f"(d[0]), "+f"(d[1]), "+f"(d[2]), "+f"(d[3])
        : "r"(a[0]), "r"(a[1]), "r"(a[2]), "r"(a[3]), "r"(b[0]), "r"(b[1]));
}

// ============================================================
// prep_c: hid = last_hidden @ Ua_w + Ua_b;  then
// c[b,col] = (Wa_b_h @ Wa2)[j] + Wa2_b[j] + (hid_bh @ Ua2)[j] + Ua2_b[j]
// ============================================================
__global__ void prep_c(const float* __restrict__ lh,  const float* __restrict__ Ua_w,
                       const float* __restrict__ Ua_b, const float* __restrict__ Wa_b,
                       const float* __restrict__ Wa2_w, const float* __restrict__ Wa2_b,
                       const float* __restrict__ Ua2_w, const float* __restrict__ Ua2_b) {
    __shared__ float hid[ATTN_];
    int b = blockIdx.x, col = threadIdx.x;
    float acc = Ua_b[col];
    for (int f = 0; f < FEAT_; f++) acc += lh[b * FEAT_ + f] * Ua_w[f * ATTN_ + col];
    hid[col] = acc;
    __syncthreads();
    int h = col >> 6, j = col & 63;
    float c = Wa2_b[j] + Ua2_b[j];
    for (int k = 0; k < HD_; k++) {
        c += hid[h * HD_ + k] * Ua2_w[k * HD_ + j];
        c += Wa_b[h * HD_ + k] * Wa2_w[k * HD_ + j];
    }
    g_c[b * ATTN_ + col] = c;
}

// ============================================================
// prep_M: M[f, h*64+j] = sum_k Wa_w[f, h*64+k] * Wa2_w[k, j]
// stored as fp16, K-major: g_Mh[col * 512 + f]
// ============================================================
__global__ void prep_M(const float* __restrict__ Wa_w, const float* __restrict__ Wa2_w) {
    __shared__ float wrow[ATTN_];
    int f = blockIdx.x, col = threadIdx.x;
    wrow[col] = Wa_w[f * ATTN_ + col];
    __syncthreads();
    int h = col >> 6, j = col & 63;
    float acc = 0.f;
    for (int k = 0; k < HD_; k++) acc += wrow[h * HD_ + k] * Wa2_w[k * HD_ + j];
    g_Mh[col * FEAT_ + f] = __float2half_rn(acc);
}

// ============================================================
// passA_mma: T = X @ M via mma.sync fp16 m16n8k16 (f32 acc); tanh+va-dot.
// CTA: BM=256 x BN=128 (2 heads), BK=32, 3-stage cp.async, occ 1.
// 512 threads = 16 warps: 8(M) x 2(N); per-warp tile 32x64 (as R7).
// Rationale: same smem traffic + barriers now feed 2x the MMA work ->
// crossbar/barrier overhead per unit work halves.
// ============================================================
#define BM     256
#define BK     32
#define NKT    (FEAT_ / BK)          // 16 chunks
#define NSTAGE 3
#define NTHR   512
#define XS_STRIDE 40                 // floats per row
#define MS_STRIDE 56                 // halves per row
#define XSZ    (BM * XS_STRIDE * 4)  // 40960 B per stage
#define MSZ    (128 * MS_STRIDE * 2) // 14336 B per stage
#define OFF_M_BASE (NSTAGE * XSZ)    // 122880
#define OFF_VA     (OFF_M_BASE + NSTAGE * MSZ)   // 165888
#define SMEM_TOT   (OFF_VA + 256)                // 166144 bytes

__global__ void __launch_bounds__(NTHR, 1) passA_mma(const float* __restrict__ X,
                                                     const float* __restrict__ va_w,
                                                     const float* __restrict__ va_b) {
    extern __shared__ char smc[];
    const uint32_t sbase = smem_u32(smc);
    const int tid = threadIdx.x;
    const int wid = tid >> 5, lane = tid & 31;
    const int q = lane >> 2, r = lane & 3;      // quad row / quad lane
    const int warp_m = wid >> 1, warp_n = wid & 1;   // 8 x 2
    const int nbase = blockIdx.x * 128;
    const int rowbase = blockIdx.y * BM;
    const int head = (nbase >> 6) + warp_n;

    if (tid < 64) ((float*)(smc + OFF_VA))[tid] = va_w[tid];

    // ---- chunk loader: X 2048x16B + M 512x16B => 5 cp.async / thread ----
    auto load_chunk = [&](int kt, int st) {
        int k0 = kt * BK;
        uint32_t xb = sbase + st * XSZ;
        uint32_t mb = sbase + OFF_M_BASE + st * MSZ;
#pragma unroll
        for (int t = 0; t < 4; t++) {
            int g = tid + t * NTHR;
            int row = g >> 3, qq = g & 7;       // 8 x 16B per 32-float row
            uint32_t dst = xb + row * (XS_STRIDE * 4) + qq * 16;
            const float* src = X + (size_t)(rowbase + row) * FEAT_ + k0 + qq * 4;
            CP_ASYNC16(dst, src);
        }
        {
            int g = tid;
            int n = g >> 2, qq = g & 3;         // 4 x 16B per 32-half row
            uint32_t dst = mb + n * (MS_STRIDE * 2) + qq * 16;
            const __half* src = g_Mh + (size_t)(nbase + n) * FEAT_ + k0 + qq * 8;
            CP_ASYNC16(dst, src);
        }
        CP_COMMIT();
    };

    float acc[2][8][4];
#pragma unroll
    for (int mt = 0; mt < 2; mt++)
#pragma unroll
        for (int nt = 0; nt < 8; nt++)
#pragma unroll
            for (int e = 0; e < 4; e++) acc[mt][nt][e] = 0.f;

    // preamble: fill stages 0,1
    load_chunk(0, 0);
    load_chunk(1, 1);

    int bf = 0;                                  // stage of chunk kt
    int bn = 2;                                  // stage for chunk kt+2
    for (int kt = 0; kt < NKT; kt++) {
        if (kt < NKT - 1) { CP_WAIT(1); }        // group kt complete (kt+1 may pend)
        else             { CP_WAIT(0); }
        __syncthreads();                          // visibility + all warps done with kt-1
        if (kt + 2 < NKT) load_chunk(kt + 2, bn); // into buffer freed by chunk kt-1

        const float* xs = (const float*)(smc + bf * XSZ);
        const __half* ms = (const __half*)(smc + OFF_M_BASE + bf * MSZ);
#pragma unroll
        for (int kk = 0; kk < 2; kk++) {        // two k16 steps per 32-chunk
            int k0 = kk * 16;
            uint32_t afr[2][4];
#pragma unroll
            for (int mt = 0; mt < 2; mt++) {
                int row = warp_m * 32 + mt * 16 + q;
                float2 v0 = *reinterpret_cast<const float2*>(&xs[row * XS_STRIDE + k0 + r * 2]);
                float2 v1 = *reinterpret_cast<const float2*>(&xs[(row + 8) * XS_STRIDE + k0 + r * 2]);
                float2 v2 = *reinterpret_cast<const float2*>(&xs[row * XS_STRIDE + k0 + r * 2 + 8]);
                float2 v3 = *reinterpret_cast<const float2*>(&xs[(row + 8) * XS_STRIDE + k0 + r * 2 + 8]);
                afr[mt][0] = pack_h2(v0.x, v0.y);
                afr[mt][1] = pack_h2(v1.x, v1.y);
                afr[mt][2] = pack_h2(v2.x, v2.y);
                afr[mt][3] = pack_h2(v3.x, v3.y);
            }
            uint32_t bfr[8][2];
#pragma unroll
            for (int nt = 0; nt < 8; nt++) {
                int n = warp_n * 64 + nt * 8 + q;
                bfr[nt][0] = *reinterpret_cast<const uint32_t*>(&ms[n * MS_STRIDE + k0 + r * 2]);
                bfr[nt][1] = *reinterpret_cast<const uint32_t*>(&ms[n * MS_STRIDE + k0 + r * 2 + 8]);
            }
#pragma unroll
            for (int mt = 0; mt < 2; mt++)
#pragma unroll
                for (int nt = 0; nt < 8; nt++)
                    mma_f16(acc[mt][nt], afr[mt], bfr[nt]);
        }
        bf = (bf == NSTAGE - 1) ? 0 : bf + 1;
        bn = (bn == NSTAGE - 1) ? 0 : bn + 1;
    }

    // ---- epilogue: tanh + va-dot, quad reduction, score write ----
    float vb = va_b[0];
    const float* va_s = (const float*)(smc + OFF_VA);
#pragma unroll
    for (int mt = 0; mt < 2; mt++) {
#pragma unroll
        for (int ro = 0; ro < 2; ro++) {
            int rglob = rowbase + warp_m * 32 + mt * 16 + q + ro * 8;
            int b = rglob & (B_ - 1), p = rglob >> 5;
            const float* crow = &g_c[b * ATTN_ + head * HD_];
            float s = 0.f;
#pragma unroll
            for (int nt = 0; nt < 8; nt++) {
                int col = nt * 8 + r * 2;
                float2 cc = *reinterpret_cast<const float2*>(&crow[col]);
                s += tanha(acc[mt][nt][ro * 2 + 0] + cc.x) * va_s[col];
                s += tanha(acc[mt][nt][ro * 2 + 1] + cc.y) * va_s[col + 1];
            }
            s += __shfl_xor_sync(0xffffffffu, s, 1, 4);
            s += __shfl_xor_sync(0xffffffffu, s, 2, 4);
            if (r == 0) g_scores[(b * NH_ + head) * P_ + p] = s + vb;
        }
    }
}

// ============================================================
// passB: softmax stats (max, sum-exp) over P per (b,h)
// ============================================================
__global__ void passB() {
    int bh = blockIdx.x;
    const float* s = &g_scores[bh * P_];
    __shared__ float red[256];
    int tid = threadIdx.x;
    float m = -1e30f;
    for (int i = tid; i < P_; i += 256) m = fmaxf(m, s[i]);
    red[tid] = m; __syncthreads();
    for (int st = 128; st > 0; st >>= 1) {
        if (tid < st) red[tid] = fmaxf(red[tid], red[tid + st]);
        __syncthreads();
    }
    m = red[0]; __syncthreads();
    float l = 0.f;
    for (int i = tid; i < P_; i += 256) l += expf(s[i] - m);
    red[tid] = l; __syncthreads();
    for (int st = 128; st > 0; st >>= 1) {
        if (tid < st) red[tid] += red[tid + st];
        __syncthreads();
    }
    if (tid == 0) { g_m[bh] = m; g_l[bh] = red[0]; }
}

// ============================================================
// passC: per (chunk, b): w = exp(s-m)/l; writes weight output;
// partial y_{b,h} += sum_p w * x_pb (deterministic per-chunk partials)
// ============================================================
__global__ __launch_bounds__(256) void passC(const float* __restrict__ X, float* __restrict__ out) {
    int chunk = blockIdx.x, b = blockIdx.y;
    int p0 = chunk * PCH;
    int tid = threadIdx.x;
    __shared__ float m_s[NH_], li_s[NH_];
    __shared__ float w_s[PCH * NH_];   // [p_local][h]
    if (tid < NH_) { m_s[tid] = g_m[b * NH_ + tid]; li_s[tid] = 1.f / g_l[b * NH_ + tid]; }
    __syncthreads();
    for (int idx = tid; idx < PCH * NH_; idx += 256) {
        int pl = idx >> 3, h = idx & 7;
        float s = g_scores[(b * NH_ + h) * P_ + p0 + pl];
        w_s[idx] = expf(s - m_s[h]) * li_s[h];
    }
    __syncthreads();
    // weight output = mean over heads
    if (tid < PCH) {
        float sum = 0.f;
#pragma unroll
        for (int h = 0; h < NH_; h++) sum += w_s[tid * NH_ + h];
        out[CTX_N + (p0 + tid) * B_ + b] = sum * (1.0f / NH_);
    }
    // weighted reduction of X rows; each thread owns cols tid and tid+256
    float acc[NH_][2];
#pragma unroll
    for (int h = 0; h < NH_; h++) { acc[h][0] = 0.f; acc[h][1] = 0.f; }
#pragma unroll 4
    for (int pl = 0; pl < PCH; pl++) {
        const float* xr = &X[(size_t)((p0 + pl) * B_ + b) * FEAT_];
        float x0 = xr[tid], x1 = xr[tid + 256];
#pragma unroll
        for (int h = 0; h < NH_; h++) {
            float w = w_s[pl * NH_ + h];
            acc[h][0] += w * x0;
            acc[h][1] += w * x1;
        }
    }
    float* yp = &g_ypart[(size_t)chunk * (B_ * NH_ * FEAT_) + (b * NH_) * FEAT_];
#pragma unroll
    for (int h = 0; h < NH_; h++) {
        yp[h * FEAT_ + tid]       = acc[h][0];
        yp[h * FEAT_ + tid + 256] = acc[h][1];
    }
}

// ============================================================
// passD: y = sum over chunks of partials; context = y @ Wa_w(head slice) + Wa_b
// ============================================================
__global__ void passD(const float* __restrict__ Wa_w, const float* __restrict__ Wa_b,
                      float* __restrict__ out) {
    int b = blockIdx.x, col = threadIdx.x;
    __shared__ float y_s[NH_ * FEAT_];
    for (int idx = col; idx < NH_ * FEAT_; idx += 512) {
        float acc = 0.f;
        for (int ch = 0; ch < NCHUNK; ch++)
            acc += g_ypart[(size_t)ch * (B_ * NH_ * FEAT_) + b * (NH_ * FEAT_) + idx];
        y_s[idx] = acc;
    }
    __syncthreads();
    int h = col >> 6;
    float acc = Wa_b[col];
    const float* yrow = &y_s[h * FEAT_];
    for (int f = 0; f < FEAT_; f++) acc += yrow[f] * Wa_w[f * ATTN_ + col];
    out[b * ATTN_ + col] = acc;
}

// ============================================================
extern "C" void kernel_launch(void* const* d_in, const int* in_sizes, int n_in,
                              void* d_out, int out_size) {
    (void)in_sizes; (void)n_in; (void)out_size;
    const float* lh    = (const float*)d_in[0];   // last_hidden   [1,B,512]
    const float* X     = (const float*)d_in[1];   // encoder_outputs [P,B,512]
    const float* Wa_w  = (const float*)d_in[2];
    const float* Wa_b  = (const float*)d_in[3];
    const float* Ua_w  = (const float*)d_in[4];
    const float* Ua_b  = (const float*)d_in[5];
    const float* Wa2_w = (const float*)d_in[6];
    const float* Wa2_b = (const float*)d_in[7];
    const float* Ua2_w = (const float*)d_in[8];
    const float* Ua2_b = (const float*)d_in[9];
    const float* va_w  = (const float*)d_in[10];
    const float* va_b  = (const float*)d_in[11];
    float* out = (float*)d_out;

    cudaFuncSetAttribute(passA_mma, cudaFuncAttributeMaxDynamicSharedMemorySize, SMEM_TOT);

    prep_c<<<B_, ATTN_>>>(lh, Ua_w, Ua_b, Wa_b, Wa2_w, Wa2_b, Ua2_w, Ua2_b);
    prep_M<<<FEAT_, ATTN_>>>(Wa_w, Wa2_w);
    passA_mma<<<dim3(ATTN_ / 128, NROWS / BM), NTHR, SMEM_TOT>>>(X, va_w, va_b);
    passB<<<B_ * NH_, 256>>>();
    passC<<<dim3(NCHUNK, B_), 256>>>(X, out);
    passD<<<B_, ATTN_>>>(Wa_w, Wa_b, out);
}

// round 14
// speedup vs baseline: 1.0659x; 1.0619x over previous
#include <cuda_runtime.h>
#include <cuda_fp16.h>
#include <cstdint>

// Problem constants
#define P_     4096
#define B_     32
#define FEAT_  512
#define ATTN_  512
#define NH_    8
#define HD_    64
#define NROWS  (P_ * B_)          // 131072 rows of X (p,b)
#define CTX_N  (B_ * ATTN_)       // context floats (output offset for weight)
#define NCHUNK 32                 // P chunks for pass C
#define PCH    (P_ / NCHUNK)      // 128 pixels per chunk

// ---- device scratch (static: allocation-free rule) ----
__device__ __half g_Xh[(size_t)NROWS * FEAT_];          // X in fp16 (128 MB)
__device__ __half g_Mh[ATTN_ * FEAT_];                  // folded weight fp16, K-major [col][f]
__device__ float g_c[B_ * ATTN_];                       // per-batch bias [b][col]
__device__ float g_scores[B_ * NH_ * P_];               // [b*8+h][p]
__device__ float g_m[B_ * NH_];
__device__ float g_l[B_ * NH_];
__device__ float g_ypart[NCHUNK * B_ * NH_ * FEAT_];    // deterministic partial sums

// ============================================================
// helpers
// ============================================================
__device__ __forceinline__ uint32_t smem_u32(const void* p) {
    uint32_t a;
    asm("{ .reg .u64 t; cvta.to.shared.u64 t, %1; cvt.u32.u64 %0, t; }" : "=r"(a) : "l"(p));
    return a;
}
__device__ __forceinline__ float tanha(float x) {
    float r;
    asm("tanh.approx.f32 %0, %1;" : "=f"(r) : "f"(x));
    return r;
}
#define CP_ASYNC16(dst, src)  asm volatile("cp.async.cg.shared.global [%0], [%1], 16;" :: "r"(dst), "l"(src))
#define CP_COMMIT()           asm volatile("cp.async.commit_group;" ::: "memory")
#define CP_WAIT(n)            asm volatile("cp.async.wait_group %0;" :: "n"(n) : "memory")

// fp16 MMA m16n8k16, fp32 accumulate
__device__ __forceinline__ void mma_f16(float* d, const uint32_t* a, const uint32_t* b) {
    asm volatile(
        "mma.sync.aligned.m16n8k16.row.col.f32.f16.f16.f32 "
        "{%0,%1,%2,%3}, {%4,%5,%6,%7}, {%8,%9}, {%0,%1,%2,%3};"
        : "+f"(d[0]), "+f"(d[1]), "+f"(d[2]), "+f"(d[3])
        : "r"(a[0]), "r"(a[1]), "r"(a[2]), "r"(a[3]), "r"(b[0]), "r"(b[1]));
}

// ============================================================
// prep_X: X fp32 -> g_Xh fp16 (rn), vectorized. 16.7M float4 units.
// ============================================================
__global__ void prep_X(const float4* __restrict__ X4) {
    size_t i = (size_t)blockIdx.x * blockDim.x + threadIdx.x;
    float4 v = X4[i];
    __half2* dst = reinterpret_cast<__half2*>(g_Xh) + i * 2;
    dst[0] = __floats2half2_rn(v.x, v.y);
    dst[1] = __floats2half2_rn(v.z, v.w);
}

// ============================================================
// prep_c: hid = last_hidden @ Ua_w + Ua_b;  then
// c[b,col] = (Wa_b_h @ Wa2)[j] + Wa2_b[j] + (hid_bh @ Ua2)[j] + Ua2_b[j]
// ============================================================
__global__ void prep_c(const float* __restrict__ lh,  const float* __restrict__ Ua_w,
                       const float* __restrict__ Ua_b, const float* __restrict__ Wa_b,
                       const float* __restrict__ Wa2_w, const float* __restrict__ Wa2_b,
                       const float* __restrict__ Ua2_w, const float* __restrict__ Ua2_b) {
    __shared__ float hid[ATTN_];
    int b = blockIdx.x, col = threadIdx.x;
    float acc = Ua_b[col];
    for (int f = 0; f < FEAT_; f++) acc += lh[b * FEAT_ + f] * Ua_w[f * ATTN_ + col];
    hid[col] = acc;
    __syncthreads();
    int h = col >> 6, j = col & 63;
    float c = Wa2_b[j] + Ua2_b[j];
    for (int k = 0; k < HD_; k++) {
        c += hid[h * HD_ + k] * Ua2_w[k * HD_ + j];
        c += Wa_b[h * HD_ + k] * Wa2_w[k * HD_ + j];
    }
    g_c[b * ATTN_ + col] = c;
}

// ============================================================
// prep_M: M[f, h*64+j] = sum_k Wa_w[f, h*64+k] * Wa2_w[k, j]
// stored as fp16, K-major: g_Mh[col * 512 + f]
// ============================================================
__global__ void prep_M(const float* __restrict__ Wa_w, const float* __restrict__ Wa2_w) {
    __shared__ float wrow[ATTN_];
    int f = blockIdx.x, col = threadIdx.x;
    wrow[col] = Wa_w[f * ATTN_ + col];
    __syncthreads();
    int h = col >> 6, j = col & 63;
    float acc = 0.f;
    for (int k = 0; k < HD_; k++) acc += wrow[h * HD_ + k] * Wa2_w[k * HD_ + j];
    g_Mh[col * FEAT_ + f] = __float2half_rn(acc);
}

// ============================================================
// passA_mma: T = Xh @ M via mma.sync fp16 (f32 acc); tanh + va-dot -> scores.
// CTA: BM=128 x BN=128 (2 heads), BK=32, 3-stage cp.async, occ 2.
// 8 warps: 4(M) x 2(N); warp tile 32x64.
// Xs: fp16, stride 40 halves (banks (20q+r) mod 32 all-distinct -> conflict-free)
// Ms: fp16 K-major, stride 56 halves (conflict-free)
// ============================================================
#define BK     32
#define NKT    (FEAT_ / BK)          // 16 chunks
#define NSTAGE 3
#define XS_STRIDE 40                 // halves per row
#define MS_STRIDE 56                 // halves per row
#define XSZ    (128 * XS_STRIDE * 2) // 10240 B per stage
#define MSZ    (128 * MS_STRIDE * 2) // 14336 B per stage
#define OFF_M_BASE (NSTAGE * XSZ)    // 30720
#define OFF_VA     (OFF_M_BASE + NSTAGE * MSZ)   // 73728
#define SMEM_TOT   (OFF_VA + 256)                // 73984 bytes

__global__ void __launch_bounds__(256, 2) passA_mma(const float* __restrict__ va_w,
                                                    const float* __restrict__ va_b) {
    extern __shared__ char smc[];
    const uint32_t sbase = smem_u32(smc);
    const int tid = threadIdx.x;
    const int wid = tid >> 5, lane = tid & 31;
    const int q = lane >> 2, r = lane & 3;      // quad row / quad lane
    const int warp_m = wid & 3, warp_n = wid >> 2;
    const int nbase = blockIdx.x * 128;
    const int rowbase = blockIdx.y * 128;
    const int head = (nbase >> 6) + warp_n;

    if (tid < 64) ((float*)(smc + OFF_VA))[tid] = va_w[tid];

    // ---- chunk loader: X 512x16B + M 512x16B => 4 cp.async / thread ----
    auto load_chunk = [&](int kt, int st) {
        int k0 = kt * BK;
        uint32_t xb = sbase + st * XSZ;
        uint32_t mb = sbase + OFF_M_BASE + st * MSZ;
#pragma unroll
        for (int t = 0; t < 2; t++) {
            int g = tid + t * 256;
            int row = g >> 2, qq = g & 3;       // 4 x 16B per 32-half row
            uint32_t dst = xb + row * (XS_STRIDE * 2) + qq * 16;
            const __half* src = g_Xh + (size_t)(rowbase + row) * FEAT_ + k0 + qq * 8;
            CP_ASYNC16(dst, src);
        }
#pragma unroll
        for (int t = 0; t < 2; t++) {
            int g = tid + t * 256;
            int n = g >> 2, qq = g & 3;         // 4 x 16B per 32-half row
            uint32_t dst = mb + n * (MS_STRIDE * 2) + qq * 16;
            const __half* src = g_Mh + (size_t)(nbase + n) * FEAT_ + k0 + qq * 8;
            CP_ASYNC16(dst, src);
        }
        CP_COMMIT();
    };

    float acc[2][8][4];
#pragma unroll
    for (int mt = 0; mt < 2; mt++)
#pragma unroll
        for (int nt = 0; nt < 8; nt++)
#pragma unroll
            for (int e = 0; e < 4; e++) acc[mt][nt][e] = 0.f;

    // preamble: fill stages 0,1
    load_chunk(0, 0);
    load_chunk(1, 1);

    int bf = 0;                                  // stage of chunk kt
    int bn = 2;                                  // stage for chunk kt+2
    for (int kt = 0; kt < NKT; kt++) {
        if (kt < NKT - 1) { CP_WAIT(1); }        // group kt complete (kt+1 may pend)
        else             { CP_WAIT(0); }
        __syncthreads();                          // visibility + all warps done with kt-1
        if (kt + 2 < NKT) load_chunk(kt + 2, bn); // into buffer freed by chunk kt-1

        const __half* xs = (const __half*)(smc + bf * XSZ);
        const __half* ms = (const __half*)(smc + OFF_M_BASE + bf * MSZ);
#pragma unroll
        for (int kk = 0; kk < 2; kk++) {        // two k16 steps per 32-chunk
            int k0 = kk * 16;
            uint32_t afr[2][4];
#pragma unroll
            for (int mt = 0; mt < 2; mt++) {
                int row = warp_m * 32 + mt * 16 + q;
                afr[mt][0] = *reinterpret_cast<const uint32_t*>(&xs[row * XS_STRIDE + k0 + r * 2]);
                afr[mt][1] = *reinterpret_cast<const uint32_t*>(&xs[(row + 8) * XS_STRIDE + k0 + r * 2]);
                afr[mt][2] = *reinterpret_cast<const uint32_t*>(&xs[row * XS_STRIDE + k0 + r * 2 + 8]);
                afr[mt][3] = *reinterpret_cast<const uint32_t*>(&xs[(row + 8) * XS_STRIDE + k0 + r * 2 + 8]);
            }
            uint32_t bfr[8][2];
#pragma unroll
            for (int nt = 0; nt < 8; nt++) {
                int n = warp_n * 64 + nt * 8 + q;
                bfr[nt][0] = *reinterpret_cast<const uint32_t*>(&ms[n * MS_STRIDE + k0 + r * 2]);
                bfr[nt][1] = *reinterpret_cast<const uint32_t*>(&ms[n * MS_STRIDE + k0 + r * 2 + 8]);
            }
#pragma unroll
            for (int mt = 0; mt < 2; mt++)
#pragma unroll
                for (int nt = 0; nt < 8; nt++)
                    mma_f16(acc[mt][nt], afr[mt], bfr[nt]);
        }
        bf = (bf == NSTAGE - 1) ? 0 : bf + 1;
        bn = (bn == NSTAGE - 1) ? 0 : bn + 1;
    }

    // ---- epilogue: tanh + va-dot, quad reduction, score write ----
    float vb = va_b[0];
    const float* va_s = (const float*)(smc + OFF_VA);
#pragma unroll
    for (int mt = 0; mt < 2; mt++) {
#pragma unroll
        for (int ro = 0; ro < 2; ro++) {
            int rglob = rowbase + warp_m * 32 + mt * 16 + q + ro * 8;
            int b = rglob & (B_ - 1), p = rglob >> 5;
            const float* crow = &g_c[b * ATTN_ + head * HD_];
            float s = 0.f;
#pragma unroll
            for (int nt = 0; nt < 8; nt++) {
                int col = nt * 8 + r * 2;
                float2 cc = *reinterpret_cast<const float2*>(&crow[col]);
                s += tanha(acc[mt][nt][ro * 2 + 0] + cc.x) * va_s[col];
                s += tanha(acc[mt][nt][ro * 2 + 1] + cc.y) * va_s[col + 1];
            }
            s += __shfl_xor_sync(0xffffffffu, s, 1, 4);
            s += __shfl_xor_sync(0xffffffffu, s, 2, 4);
            if (r == 0) g_scores[(b * NH_ + head) * P_ + p] = s + vb;
        }
    }
}

// ============================================================
// passB: softmax stats (max, sum-exp) over P per (b,h)
// ============================================================
__global__ void passB() {
    int bh = blockIdx.x;
    const float* s = &g_scores[bh * P_];
    __shared__ float red[256];
    int tid = threadIdx.x;
    float m = -1e30f;
    for (int i = tid; i < P_; i += 256) m = fmaxf(m, s[i]);
    red[tid] = m; __syncthreads();
    for (int st = 128; st > 0; st >>= 1) {
        if (tid < st) red[tid] = fmaxf(red[tid], red[tid + st]);
        __syncthreads();
    }
    m = red[0]; __syncthreads();
    float l = 0.f;
    for (int i = tid; i < P_; i += 256) l += expf(s[i] - m);
    red[tid] = l; __syncthreads();
    for (int st = 128; st > 0; st >>= 1) {
        if (tid < st) red[tid] += red[tid + st];
        __syncthreads();
    }
    if (tid == 0) { g_m[bh] = m; g_l[bh] = red[0]; }
}

// ============================================================
// passC: per (chunk, b): w = exp(s-m)/l; writes weight output;
// partial y_{b,h} += sum_p w * x_pb (deterministic per-chunk partials)
// X read as fp16 (g_Xh) -> half the DRAM bytes.
// ============================================================
__global__ __launch_bounds__(256) void passC(float* __restrict__ out) {
    int chunk = blockIdx.x, b = blockIdx.y;
    int p0 = chunk * PCH;
    int tid = threadIdx.x;
    __shared__ float m_s[NH_], li_s[NH_];
    __shared__ float w_s[PCH * NH_];   // [p_local][h]
    if (tid < NH_) { m_s[tid] = g_m[b * NH_ + tid]; li_s[tid] = 1.f / g_l[b * NH_ + tid]; }
    __syncthreads();
    for (int idx = tid; idx < PCH * NH_; idx += 256) {
        int pl = idx >> 3, h = idx & 7;
        float s = g_scores[(b * NH_ + h) * P_ + p0 + pl];
        w_s[idx] = expf(s - m_s[h]) * li_s[h];
    }
    __syncthreads();
    // weight output = mean over heads
    if (tid < PCH) {
        float sum = 0.f;
#pragma unroll
        for (int h = 0; h < NH_; h++) sum += w_s[tid * NH_ + h];
        out[CTX_N + (p0 + tid) * B_ + b] = sum * (1.0f / NH_);
    }
    // weighted reduction of X rows; each thread owns cols tid and tid+256
    float acc[NH_][2];
#pragma unroll
    for (int h = 0; h < NH_; h++) { acc[h][0] = 0.f; acc[h][1] = 0.f; }
#pragma unroll 4
    for (int pl = 0; pl < PCH; pl++) {
        const __half* xr = &g_Xh[(size_t)((p0 + pl) * B_ + b) * FEAT_];
        float x0 = __half2float(xr[tid]), x1 = __half2float(xr[tid + 256]);
#pragma unroll
        for (int h = 0; h < NH_; h++) {
            float w = w_s[pl * NH_ + h];
            acc[h][0] += w * x0;
            acc[h][1] += w * x1;
        }
    }
    float* yp = &g_ypart[(size_t)chunk * (B_ * NH_ * FEAT_) + (b * NH_) * FEAT_];
#pragma unroll
    for (int h = 0; h < NH_; h++) {
        yp[h * FEAT_ + tid]       = acc[h][0];
        yp[h * FEAT_ + tid + 256] = acc[h][1];
    }
}

// ============================================================
// passD: y = sum over chunks of partials; context = y @ Wa_w(head slice) + Wa_b
// ============================================================
__global__ void passD(const float* __restrict__ Wa_w, const float* __restrict__ Wa_b,
                      float* __restrict__ out) {
    int b = blockIdx.x, col = threadIdx.x;
    __shared__ float y_s[NH_ * FEAT_];
    for (int idx = col; idx < NH_ * FEAT_; idx += 512) {
        float acc = 0.f;
        for (int ch = 0; ch < NCHUNK; ch++)
            acc += g_ypart[(size_t)ch * (B_ * NH_ * FEAT_) + b * (NH_ * FEAT_) + idx];
        y_s[idx] = acc;
    }
    __syncthreads();
    int h = col >> 6;
    float acc = Wa_b[col];
    const float* yrow = &y_s[h * FEAT_];
    for (int f = 0; f < FEAT_; f++) acc += yrow[f] * Wa_w[f * ATTN_ + col];
    out[b * ATTN_ + col] = acc;
}

// ============================================================
extern "C" void kernel_launch(void* const* d_in, const int* in_sizes, int n_in,
                              void* d_out, int out_size) {
    (void)in_sizes; (void)n_in; (void)out_size;
    const float* lh    = (const float*)d_in[0];   // last_hidden   [1,B,512]
    const float* X     = (const float*)d_in[1];   // encoder_outputs [P,B,512]
    const float* Wa_w  = (const float*)d_in[2];
    const float* Wa_b  = (const float*)d_in[3];
    const float* Ua_w  = (const float*)d_in[4];
    const float* Ua_b  = (const float*)d_in[5];
    const float* Wa2_w = (const float*)d_in[6];
    const float* Wa2_b = (const float*)d_in[7];
    const float* Ua2_w = (const float*)d_in[8];
    const float* Ua2_b = (const float*)d_in[9];
    const float* va_w  = (const float*)d_in[10];
    const float* va_b  = (const float*)d_in[11];
    float* out = (float*)d_out;

    cudaFuncSetAttribute(passA_mma, cudaFuncAttributeMaxDynamicSharedMemorySize, SMEM_TOT);

    prep_X<<<(NROWS * (FEAT_ / 4)) / 256, 256>>>((const float4*)X);
    prep_c<<<B_, ATTN_>>>(lh, Ua_w, Ua_b, Wa_b, Wa2_w, Wa2_b, Ua2_w, Ua2_b);
    prep_M<<<FEAT_, ATTN_>>>(Wa_w, Wa2_w);
    passA_mma<<<dim3(ATTN_ / 128, NROWS / 128), 256, SMEM_TOT>>>(va_w, va_b);
    passB<<<B_ * NH_, 256>>>();
    passC<<<dim3(NCHUNK, B_), 256>>>(out);
    passD<<<B_, ATTN_>>>(Wa_w, Wa_b, out);
}

// round 16
// speedup vs baseline: 1.1821x; 1.1091x over previous
#include <cuda_runtime.h>
#include <cuda_fp16.h>
#include <cstdint>

// Problem constants
#define P_     4096
#define B_     32
#define FEAT_  512
#define ATTN_  512
#define NH_    8
#define HD_    64
#define NROWS  (P_ * B_)          // 131072 rows of X (p,b)
#define CTX_N  (B_ * ATTN_)       // context floats (output offset for weight)
#define NCHUNK 32                 // P chunks for pass C
#define PCH    (P_ / NCHUNK)      // 128 pixels per chunk

// ---- device scratch (static: allocation-free rule) ----
__device__ __half g_Xh[(size_t)NROWS * FEAT_];          // X in fp16 (128 MB)
__device__ __half g_Mh[ATTN_ * FEAT_];                  // folded weight fp16, K-major [col][f]
__device__ float g_c[B_ * ATTN_];                       // per-batch bias [b][col]
__device__ float g_scores[B_ * NH_ * P_];               // [b*8+h][p]
__device__ float g_m[B_ * NH_];
__device__ float g_l[B_ * NH_];
__device__ float g_ypart[NCHUNK * B_ * NH_ * FEAT_];    // deterministic partial sums

// ============================================================
// helpers
// ============================================================
__device__ __forceinline__ uint32_t smem_u32(const void* p) {
    uint32_t a;
    asm("{ .reg .u64 t; cvta.to.shared.u64 t, %1; cvt.u32.u64 %0, t; }" : "=r"(a) : "l"(p));
    return a;
}
__device__ __forceinline__ float tanha(float x) {
    float r;
    asm("tanh.approx.f32 %0, %1;" : "=f"(r) : "f"(x));
    return r;
}
#define CP_ASYNC16(dst, src)  asm volatile("cp.async.cg.shared.global [%0], [%1], 16;" :: "r"(dst), "l"(src))
#define CP_COMMIT()           asm volatile("cp.async.commit_group;" ::: "memory")
#define CP_WAIT(n)            asm volatile("cp.async.wait_group %0;" :: "n"(n) : "memory")
#define LDSM4(r0, r1, r2, r3, addr) \
    asm volatile("ldmatrix.sync.aligned.m8n8.x4.shared.b16 {%0,%1,%2,%3}, [%4];" \
                 : "=r"(r0), "=r"(r1), "=r"(r2), "=r"(r3) : "r"(addr))

// fp16 MMA m16n8k16, fp32 accumulate
__device__ __forceinline__ void mma_f16(float* d, const uint32_t* a, const uint32_t* b) {
    asm volatile(
        "mma.sync.aligned.m16n8k16.row.col.f32.f16.f16.f32 "
        "{%0,%1,%2,%3}, {%4,%5,%6,%7}, {%8,%9}, {%0,%1,%2,%3};"
        : "+f"(d[0]), "+f"(d[1]), "+f"(d[2]), "+f"(d[3])
        : "r"(a[0]), "r"(a[1]), "r"(a[2]), "r"(a[3]), "r"(b[0]), "r"(b[1]));
}

// ============================================================
// prep_X: X fp32 -> g_Xh fp16 (rn). 32B read / 16B write per thread.
// ============================================================
__global__ void prep_X(const float4* __restrict__ X4) {
    size_t i = (size_t)blockIdx.x * blockDim.x + threadIdx.x;
    float4 a = X4[i * 2], b = X4[i * 2 + 1];
    __half2 h0 = __floats2half2_rn(a.x, a.y);
    __half2 h1 = __floats2half2_rn(a.z, a.w);
    __half2 h2 = __floats2half2_rn(b.x, b.y);
    __half2 h3 = __floats2half2_rn(b.z, b.w);
    uint4 o;
    o.x = *reinterpret_cast<uint32_t*>(&h0);
    o.y = *reinterpret_cast<uint32_t*>(&h1);
    o.z = *reinterpret_cast<uint32_t*>(&h2);
    o.w = *reinterpret_cast<uint32_t*>(&h3);
    reinterpret_cast<uint4*>(g_Xh)[i] = o;
}

// ============================================================
// prep_c: hid = last_hidden @ Ua_w + Ua_b;  then
// c[b,col] = (Wa_b_h @ Wa2)[j] + Wa2_b[j] + (hid_bh @ Ua2)[j] + Ua2_b[j]
// ============================================================
__global__ void prep_c(const float* __restrict__ lh,  const float* __restrict__ Ua_w,
                       const float* __restrict__ Ua_b, const float* __restrict__ Wa_b,
                       const float* __restrict__ Wa2_w, const float* __restrict__ Wa2_b,
                       const float* __restrict__ Ua2_w, const float* __restrict__ Ua2_b) {
    __shared__ float hid[ATTN_];
    int b = blockIdx.x, col = threadIdx.x;
    float acc = Ua_b[col];
    for (int f = 0; f < FEAT_; f++) acc += lh[b * FEAT_ + f] * Ua_w[f * ATTN_ + col];
    hid[col] = acc;
    __syncthreads();
    int h = col >> 6, j = col & 63;
    float c = Wa2_b[j] + Ua2_b[j];
    for (int k = 0; k < HD_; k++) {
        c += hid[h * HD_ + k] * Ua2_w[k * HD_ + j];
        c += Wa_b[h * HD_ + k] * Wa2_w[k * HD_ + j];
    }
    g_c[b * ATTN_ + col] = c;
}

// ============================================================
// prep_M: M[f, h*64+j] = sum_k Wa_w[f, h*64+k] * Wa2_w[k, j]
// stored as fp16, K-major: g_Mh[col * 512 + f]
// ============================================================
__global__ void prep_M(const float* __restrict__ Wa_w, const float* __restrict__ Wa2_w) {
    __shared__ float wrow[ATTN_];
    int f = blockIdx.x, col = threadIdx.x;
    wrow[col] = Wa_w[f * ATTN_ + col];
    __syncthreads();
    int h = col >> 6, j = col & 63;
    float acc = 0.f;
    for (int k = 0; k < HD_; k++) acc += wrow[h * HD_ + k] * Wa2_w[k * HD_ + j];
    g_Mh[col * FEAT_ + f] = __float2half_rn(acc);
}

// ============================================================
// passA_mma: T = Xh @ M via mma.sync fp16 (f32 acc); tanh + va-dot -> scores.
// CTA: BM=128 x BN=128 (2 heads), BK=32, 3-stage cp.async, occ 2.
// 8 warps: 4(M) x 2(N); warp tile 32x64.
// Fragments loaded via ldmatrix.x4 (12 LDSM/warp/chunk vs 48 LDS.32):
//   A: rows stride 40 halves -> 8-row phases hit banks 20r mod 32 (distinct)
//   B: rows stride 56 halves -> banks 28n mod 32 (distinct) -> conflict-free
// ============================================================
#define BK     32
#define NKT    (FEAT_ / BK)          // 16 chunks
#define NSTAGE 3
#define XS_STRIDE 40                 // halves per row
#define MS_STRIDE 56                 // halves per row
#define XSZ    (128 * XS_STRIDE * 2) // 10240 B per stage
#define MSZ    (128 * MS_STRIDE * 2) // 14336 B per stage
#define OFF_M_BASE (NSTAGE * XSZ)    // 30720
#define OFF_VA     (OFF_M_BASE + NSTAGE * MSZ)   // 73728
#define SMEM_TOT   (OFF_VA + 256)                // 73984 bytes

__global__ void __launch_bounds__(256, 2) passA_mma(const float* __restrict__ va_w,
                                                    const float* __restrict__ va_b) {
    extern __shared__ char smc[];
    const uint32_t sbase = smem_u32(smc);
    const int tid = threadIdx.x;
    const int wid = tid >> 5, lane = tid & 31;
    const int q = lane >> 2, r = lane & 3;      // quad row / quad lane
    const int warp_m = wid & 3, warp_n = wid >> 2;
    const int nbase = blockIdx.x * 128;
    const int rowbase = blockIdx.y * 128;
    const int head = (nbase >> 6) + warp_n;

    if (tid < 64) ((float*)(smc + OFF_VA))[tid] = va_w[tid];

    // per-thread ldmatrix lane-address offsets (bytes, within a stage)
    // A x4: lanes 0-15 -> rows (lane&15) @k0; lanes 16-31 -> same rows @k0+8
    const uint32_t aoffA = (uint32_t)((warp_m * 32 + (lane & 15)) * (XS_STRIDE * 2)
                                      + (lane >> 4) * 16);
    // B x4 group i: lanes 0-7 (nt=2i rows, k0), 8-15 (nt=2i rows, k0+8),
    //               16-23 (nt=2i+1 rows, k0), 24-31 (nt=2i+1 rows, k0+8)
    const uint32_t aoffB = (uint32_t)((warp_n * 64 + (lane >> 4) * 8 + (lane & 7)) * (MS_STRIDE * 2)
                                      + ((lane >> 3) & 1) * 16);

    // ---- chunk loader: X 512x16B + M 512x16B => 4 cp.async / thread ----
    auto load_chunk = [&](int kt, int st) {
        int k0 = kt * BK;
        uint32_t xb = sbase + st * XSZ;
        uint32_t mb = sbase + OFF_M_BASE + st * MSZ;
#pragma unroll
        for (int t = 0; t < 2; t++) {
            int g = tid + t * 256;
            int row = g >> 2, qq = g & 3;       // 4 x 16B per 32-half row
            uint32_t dst = xb + row * (XS_STRIDE * 2) + qq * 16;
            const __half* src = g_Xh + (size_t)(rowbase + row) * FEAT_ + k0 + qq * 8;
            CP_ASYNC16(dst, src);
        }
#pragma unroll
        for (int t = 0; t < 2; t++) {
            int g = tid + t * 256;
            int n = g >> 2, qq = g & 3;         // 4 x 16B per 32-half row
            uint32_t dst = mb + n * (MS_STRIDE * 2) + qq * 16;
            const __half* src = g_Mh + (size_t)(nbase + n) * FEAT_ + k0 + qq * 8;
            CP_ASYNC16(dst, src);
        }
        CP_COMMIT();
    };

    float acc[2][8][4];
#pragma unroll
    for (int mt = 0; mt < 2; mt++)
#pragma unroll
        for (int nt = 0; nt < 8; nt++)
#pragma unroll
            for (int e = 0; e < 4; e++) acc[mt][nt][e] = 0.f;

    // preamble: fill stages 0,1
    load_chunk(0, 0);
    load_chunk(1, 1);

    int bf = 0;                                  // stage of chunk kt
    int bn = 2;                                  // stage for chunk kt+2
    for (int kt = 0; kt < NKT; kt++) {
        if (kt < NKT - 1) { CP_WAIT(1); }        // group kt complete (kt+1 may pend)
        else             { CP_WAIT(0); }
        __syncthreads();                          // visibility + all warps done with kt-1
        if (kt + 2 < NKT) load_chunk(kt + 2, bn); // into buffer freed by chunk kt-1

        const uint32_t aA = sbase + bf * XSZ + aoffA;
        const uint32_t aB = sbase + OFF_M_BASE + bf * MSZ + aoffB;
#pragma unroll
        for (int kk = 0; kk < 2; kk++) {        // two k16 steps per 32-chunk
            uint32_t afr[2][4];
#pragma unroll
            for (int mt = 0; mt < 2; mt++)
                LDSM4(afr[mt][0], afr[mt][1], afr[mt][2], afr[mt][3],
                      aA + mt * (16 * XS_STRIDE * 2) + kk * 32);
            uint32_t bfr[8][2];
#pragma unroll
            for (int i = 0; i < 4; i++)
                LDSM4(bfr[2 * i][0], bfr[2 * i][1], bfr[2 * i + 1][0], bfr[2 * i + 1][1],
                      aB + i * (16 * MS_STRIDE * 2) + kk * 32);
#pragma unroll
            for (int mt = 0; mt < 2; mt++)
#pragma unroll
                for (int nt = 0; nt < 8; nt++)
                    mma_f16(acc[mt][nt], afr[mt], bfr[nt]);
        }
        bf = (bf == NSTAGE - 1) ? 0 : bf + 1;
        bn = (bn == NSTAGE - 1) ? 0 : bn + 1;
    }

    // ---- epilogue: tanh + va-dot, quad reduction, score write ----
    float vb = va_b[0];
    const float* va_s = (const float*)(smc + OFF_VA);
#pragma unroll
    for (int mt = 0; mt < 2; mt++) {
#pragma unroll
        for (int ro = 0; ro < 2; ro++) {
            int rglob = rowbase + warp_m * 32 + mt * 16 + q + ro * 8;
            int b = rglob & (B_ - 1), p = rglob >> 5;
            const float* crow = &g_c[b * ATTN_ + head * HD_];
            float s = 0.f;
#pragma unroll
            for (int nt = 0; nt < 8; nt++) {
                int col = nt * 8 + r * 2;
                float2 cc = *reinterpret_cast<const float2*>(&crow[col]);
                s += tanha(acc[mt][nt][ro * 2 + 0] + cc.x) * va_s[col];
                s += tanha(acc[mt][nt][ro * 2 + 1] + cc.y) * va_s[col + 1];
            }
            s += __shfl_xor_sync(0xffffffffu, s, 1, 4);
            s += __shfl_xor_sync(0xffffffffu, s, 2, 4);
            if (r == 0) g_scores[(b * NH_ + head) * P_ + p] = s + vb;
        }
    }
}

// ============================================================
// passB: softmax stats (max, sum-exp) over P per (b,h)
// ============================================================
__global__ void passB() {
    int bh = blockIdx.x;
    const float* s = &g_scores[bh * P_];
    __shared__ float red[256];
    int tid = threadIdx.x;
    float m = -1e30f;
    for (int i = tid; i < P_; i += 256) m = fmaxf(m, s[i]);
    red[tid] = m; __syncthreads();
    for (int st = 128; st > 0; st >>= 1) {
        if (tid < st) red[tid] = fmaxf(red[tid], red[tid + st]);
        __syncthreads();
    }
    m = red[0]; __syncthreads();
    float l = 0.f;
    for (int i = tid; i < P_; i += 256) l += expf(s[i] - m);
    red[tid] = l; __syncthreads();
    for (int st = 128; st > 0; st >>= 1) {
        if (tid < st) red[tid] += red[tid + st];
        __syncthreads();
    }
    if (tid == 0) { g_m[bh] = m; g_l[bh] = red[0]; }
}

// ============================================================
// passC: per (chunk, b): w = exp(s-m)/l; writes weight output;
// partial y_{b,h} += sum_p w * x_pb (deterministic per-chunk partials)
// X read as fp16 half2 (one 4B load per thread per row).
// ============================================================
__global__ __launch_bounds__(256) void passC(float* __restrict__ out) {
    int chunk = blockIdx.x, b = blockIdx.y;
    int p0 = chunk * PCH;
    int tid = threadIdx.x;
    __shared__ float m_s[NH_], li_s[NH_];
    __shared__ float w_s[PCH * NH_];   // [p_local][h]
    if (tid < NH_) { m_s[tid] = g_m[b * NH_ + tid]; li_s[tid] = 1.f / g_l[b * NH_ + tid]; }
    __syncthreads();
    for (int idx = tid; idx < PCH * NH_; idx += 256) {
        int pl = idx >> 3, h = idx & 7;
        float s = g_scores[(b * NH_ + h) * P_ + p0 + pl];
        w_s[idx] = expf(s - m_s[h]) * li_s[h];
    }
    __syncthreads();
    // weight output = mean over heads
    if (tid < PCH) {
        float sum = 0.f;
#pragma unroll
        for (int h = 0; h < NH_; h++) sum += w_s[tid * NH_ + h];
        out[CTX_N + (p0 + tid) * B_ + b] = sum * (1.0f / NH_);
    }
    // weighted reduction of X rows; thread owns cols 2*tid, 2*tid+1 (one half2)
    float acc[NH_][2];
#pragma unroll
    for (int h = 0; h < NH_; h++) { acc[h][0] = 0.f; acc[h][1] = 0.f; }
#pragma unroll 4
    for (int pl = 0; pl < PCH; pl++) {
        const __half2* xr = reinterpret_cast<const __half2*>(
            &g_Xh[(size_t)((p0 + pl) * B_ + b) * FEAT_]);
        float2 xv = __half22float2(xr[tid]);
#pragma unroll
        for (int h = 0; h < NH_; h++) {
            float w = w_s[pl * NH_ + h];
            acc[h][0] += w * xv.x;
            acc[h][1] += w * xv.y;
        }
    }
    float* yp = &g_ypart[(size_t)chunk * (B_ * NH_ * FEAT_) + (b * NH_) * FEAT_];
#pragma unroll
    for (int h = 0; h < NH_; h++)
        *reinterpret_cast<float2*>(&yp[h * FEAT_ + 2 * tid]) = make_float2(acc[h][0], acc[h][1]);
}

// ============================================================
// passD: y = sum over chunks of partials; context = y @ Wa_w(head slice) + Wa_b
// ============================================================
__global__ void passD(const float* __restrict__ Wa_w, const float* __restrict__ Wa_b,
                      float* __restrict__ out) {
    int b = blockIdx.x, col = threadIdx.x;
    __shared__ float y_s[NH_ * FEAT_];
    for (int idx = col; idx < NH_ * FEAT_; idx += 512) {
        float acc = 0.f;
        for (int ch = 0; ch < NCHUNK; ch++)
            acc += g_ypart[(size_t)ch * (B_ * NH_ * FEAT_) + b * (NH_ * FEAT_) + idx];
        y_s[idx] = acc;
    }
    __syncthreads();
    int h = col >> 6;
    float acc = Wa_b[col];
    const float* yrow = &y_s[h * FEAT_];
    for (int f = 0; f < FEAT_; f++) acc += yrow[f] * Wa_w[f * ATTN_ + col];
    out[b * ATTN_ + col] = acc;
}

// ============================================================
extern "C" void kernel_launch(void* const* d_in, const int* in_sizes, int n_in,
                              void* d_out, int out_size) {
    (void)in_sizes; (void)n_in; (void)out_size;
    const float* lh    = (const float*)d_in[0];   // last_hidden   [1,B,512]
    const float* X     = (const float*)d_in[1];   // encoder_outputs [P,B,512]
    const float* Wa_w  = (const float*)d_in[2];
    const float* Wa_b  = (const float*)d_in[3];
    const float* Ua_w  = (const float*)d_in[4];
    const float* Ua_b  = (const float*)d_in[5];
    const float* Wa2_w = (const float*)d_in[6];
    const float* Wa2_b = (const float*)d_in[7];
    const float* Ua2_w = (const float*)d_in[8];
    const float* Ua2_b = (const float*)d_in[9];
    const float* va_w  = (const float*)d_in[10];
    const float* va_b  = (const float*)d_in[11];
    float* out = (float*)d_out;

    cudaFuncSetAttribute(passA_mma, cudaFuncAttributeMaxDynamicSharedMemorySize, SMEM_TOT);

    prep_X<<<(NROWS * (FEAT_ / 8)) / 256, 256>>>((const float4*)X);
    prep_c<<<B_, ATTN_>>>(lh, Ua_w, Ua_b, Wa_b, Wa2_w, Wa2_b, Ua2_w, Ua2_b);
    prep_M<<<FEAT_, ATTN_>>>(Wa_w, Wa2_w);
    passA_mma<<<dim3(ATTN_ / 128, NROWS / 128), 256, SMEM_TOT>>>(va_w, va_b);
    passB<<<B_ * NH_, 256>>>();
    passC<<<dim3(NCHUNK, B_), 256>>>(out);
    passD<<<B_, ATTN_>>>(Wa_w, Wa_b, out);
}